// round 15
// baseline (speedup 1.0000x reference)
#include <cuda_runtime.h>
#include <cuda_fp16.h>
#include <math.h>

#define WIN   11
#define RAD   5
#define TSX   32
#define TSY   22
#define INWX  42              // TSX + 2*RAD
#define INWY  32              // TSY + 2*RAD
#define PR    45              // raw pitch in 8B units (odd -> CF row-walk LDS.64)
#define PHB   33              // hb pitch in ull2 units (odd -> CF stores + v-loads)
#define NTHREADS 256
#define GRIDY 24              // ceil(512/22)
#define NBLOCKS  (16 * GRIDY * 48)

#define C1 0.0001f
#define C2 0.0009f

struct GW { float g[WIN]; };

typedef unsigned long long f2_t;
__device__ __forceinline__ f2_t pack2(float lo, float hi) {
    f2_t r; asm("mov.b64 %0, {%1, %2};" : "=l"(r) : "f"(lo), "f"(hi)); return r;
}
__device__ __forceinline__ void unpack2(f2_t v, float& lo, float& hi) {
    asm("mov.b64 {%0, %1}, %2;" : "=f"(lo), "=f"(hi) : "l"(v));
}
__device__ __forceinline__ void fma2(f2_t& d, f2_t a, f2_t b) {
    asm("fma.rn.f32x2 %0, %1, %2, %0;" : "+l"(d) : "l"(a), "l"(b));
}
__device__ __forceinline__ f2_t mul2(f2_t a, f2_t b) {
    f2_t r; asm("mul.rn.f32x2 %0, %1, %2;" : "=l"(r) : "l"(a), "l"(b)); return r;
}

__device__ float        g_partials[NBLOCKS];
__device__ unsigned int g_done = 0;

// ---- shared layout (float units) ----
// sR  : uint2[32][45] per px: half2(A,B) | half2(F,F^2) = 2880 floats (11.5KB)
// hb0 : ull2[32][33]  (AB, AABB)  = 4224 floats (16.9KB)
// hb1 : ull2[32][33]  (AFBF, FFF) = 4224 floats (16.9KB)
#define OFF_HB0  2880
#define OFF_HB1  (OFF_HB0 + 4224)
#define OFF_RED  (OFF_HB1 + 4224)
#define SMEM_FLOATS (OFF_RED + 16)
#define SMEM_BYTES  (SMEM_FLOATS * 4)   // 45376+64 B -> 5 CTAs/SM (227KB/228KB)

__device__ __forceinline__ float ssim_val(float mu1, float mu2,
                                          float e11, float e22, float e12) {
    float mu1sq = mu1 * mu1;
    float mu2sq = mu2 * mu2;
    float mu12  = mu1 * mu2;
    float num = (2.0f * mu12 + C1) * (2.0f * (e12 - mu12) + C2);
    float den = (mu1sq + mu2sq + C1) * ((e11 - mu1sq) + (e22 - mu2sq) + C2);
    return __fdividef(num, den);
}

// symmetric taps: g[k] == g[10-k]; k compile-time at every use
#define GSYM(k) gg[(k) < 6 ? (k) : 10 - (k)]

__global__ __launch_bounds__(NTHREADS, 5)
void ssim_tile_kernel(const float* __restrict__ A,
                      const float* __restrict__ B,
                      const float* __restrict__ F,
                      GW gw,
                      float* __restrict__ out) {
    extern __shared__ float sm[];
    uint2*      sR  = (uint2*)sm;
    ulonglong2* hb0 = (ulonglong2*)(sm + OFF_HB0);
    ulonglong2* hb1 = (ulonglong2*)(sm + OFF_HB1);
    float*      red = sm + OFF_RED;

    const int tid = threadIdx.x;
    const int x0 = blockIdx.x * TSX - RAD;
    const int y0 = blockIdx.y * TSY - RAD;
    const size_t pbase = (size_t)blockIdx.z * (512 * 512);

    f2_t gg[6];
    #pragma unroll
    for (int k = 0; k < 6; k++) gg[k] = pack2(gw.g[k], gw.g[k]);

    // ---- stage raw as fp16x4: (A,B) | (F,F^2), zero-padded ----
    for (int i = tid; i < INWY * INWX; i += NTHREADS) {
        int r = i / INWX;
        int c = i - r * INWX;
        int gx = x0 + c, gy = y0 + r;
        float a = 0.f, b = 0.f, f = 0.f;
        if ((unsigned)gx < 512u && (unsigned)gy < 512u) {
            size_t off = pbase + (size_t)gy * 512 + gx;
            a = A[off]; b = B[off]; f = F[off];
        }
        __half2 hab = __floats2half2_rn(a, b);
        __half2 hff = __floats2half2_rn(f, f * f);
        uint2 st;
        st.x = *reinterpret_cast<unsigned*>(&hab);
        st.y = *reinterpret_cast<unsigned*>(&hff);
        sR[r * PR + c] = st;
    }
    __syncthreads();

    // ---- horizontal pass: 32 rows x 16 groups = 512 items = 2 full rounds ----
    for (int i = tid; i < INWY * 16; i += NTHREADS) {
        int g  = i >> 5;            // column group 0..15
        int r  = i & 31;            // row 0..31 (consecutive lanes -> consecutive rows)
        int c0 = g << 1;
        const uint2* p = sR + r * PR + c0;

        f2_t aAB[2]   = {0, 0};
        f2_t aAABB[2] = {0, 0};
        f2_t aAFBF[2] = {0, 0};
        f2_t aFFF[2]  = {0, 0};

        #pragma unroll
        for (int ii = 0; ii < 12; ii++) {
            uint2 v = p[ii];
            __half2 habh = *reinterpret_cast<__half2*>(&v.x);
            __half2 hffh = *reinterpret_cast<__half2*>(&v.y);
            float2 abf  = __half22float2(habh);
            float2 fff2 = __half22float2(hffh);
            f2_t ab   = pack2(abf.x, abf.y);
            f2_t ff2  = pack2(fff2.x, fff2.y);     // (F, F^2) = the FFF field
            f2_t ffp  = pack2(fff2.x, fff2.x);
            f2_t aabb = mul2(ab, ab);
            f2_t afbf = mul2(ab, ffp);
            #pragma unroll
            for (int j = 0; j < 2; j++) {
                int k = ii - j;
                if (k >= 0 && k < WIN) {
                    fma2(aAB[j],   GSYM(k), ab);
                    fma2(aAABB[j], GSYM(k), aabb);
                    fma2(aAFBF[j], GSYM(k), afbf);
                    fma2(aFFF[j],  GSYM(k), ff2);
                }
            }
        }
        int o = r * PHB + c0;
        #pragma unroll
        for (int j = 0; j < 2; j++) {
            hb0[o + j] = make_ulonglong2(aAB[j],   aAABB[j]);
            hb1[o + j] = make_ulonglong2(aAFBF[j], aFFF[j]);
        }
    }
    __syncthreads();

    // ---- vertical pass: thread = 1 col x 3 rows (warp 7: 1 valid row) ----
    const int vc = tid & 31;
    const int r0 = (tid >> 5) * 3;    // 0,3,...,21

    f2_t vAB[3], vAABB[3], vAFBF[3], vFFF[3];
    #pragma unroll
    for (int j = 0; j < 3; j++) { vAB[j]=0; vAABB[j]=0; vAFBF[j]=0; vFFF[j]=0; }

    #pragma unroll
    for (int ii = 0; ii < 13; ii++) {
        // clamp: warp 7's rows 32/33 would run off hb1 -> clamp to row 31.
        // Clamped data feeds only warp 7's discarded j=1,2 accumulators.
        int rr = r0 + ii; if (rr > INWY - 1) rr = INWY - 1;
        int o = rr * PHB + vc;
        ulonglong2 h0 = hb0[o];
        ulonglong2 h1 = hb1[o];
        #pragma unroll
        for (int j = 0; j < 3; j++) {
            int k = ii - j;
            if (k >= 0 && k < WIN) {
                fma2(vAB[j],   GSYM(k), h0.x);
                fma2(vAABB[j], GSYM(k), h0.y);
                fma2(vAFBF[j], GSYM(k), h1.x);
                fma2(vFFF[j],  GSYM(k), h1.y);
            }
        }
    }

    float local = 0.f;
    const int gy_base = blockIdx.y * TSY + r0;
    #pragma unroll
    for (int j = 0; j < 3; j++) {
        if (r0 + j < TSY && gy_base + j < 512) {
            float muA, muB, eAA, eBB, eAF, eBF, muF, eFF;
            unpack2(vAB[j],   muA, muB);
            unpack2(vAABB[j], eAA, eBB);
            unpack2(vAFBF[j], eAF, eBF);
            unpack2(vFFF[j],  muF, eFF);
            local += ssim_val(muA, muF, eAA, eFF, eAF);
            local += ssim_val(muB, muF, eBB, eFF, eBF);
        }
    }

    // ---- block reduction ----
    #pragma unroll
    for (int o = 16; o > 0; o >>= 1)
        local += __shfl_down_sync(0xffffffffu, local, o);
    if ((tid & 31) == 0) red[tid >> 5] = local;
    __syncthreads();

    const int bid = blockIdx.x + 16 * blockIdx.y + (16 * GRIDY) * blockIdx.z;
    __shared__ bool is_last;
    if (tid == 0) {
        float v = 0.f;
        #pragma unroll
        for (int w = 0; w < 8; w++) v += red[w];
        g_partials[bid] = v;
        __threadfence();
        unsigned int old = atomicAdd(&g_done, 1u);
        is_last = (old == NBLOCKS - 1);
    }
    __syncthreads();

    if (is_last) {
        double s = 0.0;
        for (int i = tid; i < NBLOCKS; i += NTHREADS)
            s += (double)__ldcg(&g_partials[i]);
        #pragma unroll
        for (int o = 16; o > 0; o >>= 1)
            s += __shfl_down_sync(0xffffffffu, s, o);
        double* redd = (double*)red;
        if ((tid & 31) == 0) redd[tid >> 5] = s;
        __syncthreads();
        if (tid == 0) {
            double t = 0.0;
            #pragma unroll
            for (int w = 0; w < 8; w++) t += redd[w];
            out[0] = (float)(0.5 * t / 12582912.0);
            g_done = 0;
        }
    }
}

extern "C" void kernel_launch(void* const* d_in, const int* in_sizes, int n_in,
                              void* d_out, int out_size) {
    const float* A = (const float*)d_in[0];
    const float* B = (const float*)d_in[1];
    const float* F = (const float*)d_in[2];

    GW gw;
    double gd[WIN], s = 0.0;
    for (int i = 0; i < WIN; i++) {
        double d = (double)(i - RAD);
        gd[i] = exp(-(d * d) / (2.0 * 1.5 * 1.5));
        s += gd[i];
    }
    for (int i = 0; i < WIN; i++) gw.g[i] = (float)(gd[i] / s);

    cudaFuncSetAttribute(ssim_tile_kernel,
                         cudaFuncAttributeMaxDynamicSharedMemorySize, SMEM_BYTES);

    dim3 grid(512 / TSX, GRIDY, 16 * 3);
    ssim_tile_kernel<<<grid, NTHREADS, SMEM_BYTES>>>(A, B, F, gw, (float*)d_out);
}

// round 16
// speedup vs baseline: 1.1836x; 1.1836x over previous
#include <cuda_runtime.h>
#include <cuda_fp16.h>
#include <math.h>

#define WIN   11
#define RAD   5
#define TSX   32
#define TSY   36
#define INWX  42              // TSX + 2*RAD
#define INWY  46              // TSY + 2*RAD
#define PR    43              // raw pitch in 8B units (odd -> CF row-walk LDS.64)
#define PHB   33              // hb pitch in ull2 units (odd -> CF stores + v-loads)
#define NTHREADS 384
#define NWARPS   12
#define GRIDY 15              // ceil(512/36)
#define NBLOCKS  (16 * GRIDY * 48)

#define C1 0.0001f
#define C2 0.0009f

struct GW { float g[WIN]; };

typedef unsigned long long f2_t;
__device__ __forceinline__ f2_t pack2(float lo, float hi) {
    f2_t r; asm("mov.b64 %0, {%1, %2};" : "=l"(r) : "f"(lo), "f"(hi)); return r;
}
__device__ __forceinline__ void unpack2(f2_t v, float& lo, float& hi) {
    asm("mov.b64 {%0, %1}, %2;" : "=f"(lo), "=f"(hi) : "l"(v));
}
__device__ __forceinline__ void fma2(f2_t& d, f2_t a, f2_t b) {
    asm("fma.rn.f32x2 %0, %1, %2, %0;" : "+l"(d) : "l"(a), "l"(b));
}
__device__ __forceinline__ f2_t mul2(f2_t a, f2_t b) {
    f2_t r; asm("mul.rn.f32x2 %0, %1, %2;" : "=l"(r) : "l"(a), "l"(b)); return r;
}

__device__ float        g_partials[NBLOCKS];
__device__ unsigned int g_done = 0;

// ---- shared layout (float units) ----
// sR  : uint2[46][43] per px: half2(A,B) | half2(F,F^2) = 3956 floats (15.8KB)
// hb0 : ull2[46][33]  (AB, AABB)  = 6072 floats (24.3KB)
// hb1 : ull2[46][33]  (AFBF, FFF) = 6072 floats (24.3KB)
#define OFF_HB0  3956
#define OFF_HB1  (OFF_HB0 + 6072)
#define OFF_RED  (OFF_HB1 + 6072)
#define SMEM_FLOATS (OFF_RED + 16)
#define SMEM_BYTES  (SMEM_FLOATS * 4)   // ~64.5KB -> 3 CTAs/SM (193.5/228KB)

__device__ __forceinline__ float ssim_val(float mu1, float mu2,
                                          float e11, float e22, float e12) {
    float mu1sq = mu1 * mu1;
    float mu2sq = mu2 * mu2;
    float mu12  = mu1 * mu2;
    float num = (2.0f * mu12 + C1) * (2.0f * (e12 - mu12) + C2);
    float den = (mu1sq + mu2sq + C1) * ((e11 - mu1sq) + (e22 - mu2sq) + C2);
    return __fdividef(num, den);
}

// symmetric taps: g[k] == g[10-k]; k compile-time at every use
#define GSYM(k) gg[(k) < 6 ? (k) : 10 - (k)]

__global__ __launch_bounds__(NTHREADS, 3)
void ssim_tile_kernel(const float* __restrict__ A,
                      const float* __restrict__ B,
                      const float* __restrict__ F,
                      GW gw,
                      float* __restrict__ out) {
    extern __shared__ float sm[];
    uint2*      sR  = (uint2*)sm;
    ulonglong2* hb0 = (ulonglong2*)(sm + OFF_HB0);
    ulonglong2* hb1 = (ulonglong2*)(sm + OFF_HB1);
    float*      red = sm + OFF_RED;

    const int tid = threadIdx.x;
    const int x0 = blockIdx.x * TSX - RAD;
    const int y0 = blockIdx.y * TSY - RAD;
    const size_t pbase = (size_t)blockIdx.z * (512 * 512);

    f2_t gg[6];
    #pragma unroll
    for (int k = 0; k < 6; k++) gg[k] = pack2(gw.g[k], gw.g[k]);

    // ---- stage raw as fp16x4: (A,B) | (F,F^2), zero-padded ----
    for (int i = tid; i < INWY * INWX; i += NTHREADS) {
        int r = i / INWX;
        int c = i - r * INWX;
        int gx = x0 + c, gy = y0 + r;
        float a = 0.f, b = 0.f, f = 0.f;
        if ((unsigned)gx < 512u && (unsigned)gy < 512u) {
            size_t off = pbase + (size_t)gy * 512 + gx;
            a = A[off]; b = B[off]; f = F[off];
        }
        __half2 hab = __floats2half2_rn(a, b);
        __half2 hff = __floats2half2_rn(f, f * f);
        uint2 st;
        st.x = *reinterpret_cast<unsigned*>(&hab);
        st.y = *reinterpret_cast<unsigned*>(&hff);
        sR[r * PR + c] = st;
    }
    __syncthreads();

    // ---- horizontal pass: 46 rows x 16 groups = 736 items, lanes walk rows ----
    for (int i = tid; i < INWY * 16; i += NTHREADS) {
        int g  = i / INWY;           // column group 0..15
        int r  = i - g * INWY;       // row 0..45 (consecutive lanes -> consecutive rows)
        int c0 = g << 1;
        const uint2* p = sR + r * PR + c0;

        f2_t aAB[2]   = {0, 0};
        f2_t aAABB[2] = {0, 0};
        f2_t aAFBF[2] = {0, 0};
        f2_t aFFF[2]  = {0, 0};

        #pragma unroll
        for (int ii = 0; ii < 12; ii++) {
            uint2 v = p[ii];
            __half2 habh = *reinterpret_cast<__half2*>(&v.x);
            __half2 hffh = *reinterpret_cast<__half2*>(&v.y);
            float2 abf  = __half22float2(habh);
            float2 fff2 = __half22float2(hffh);
            f2_t ab   = pack2(abf.x, abf.y);
            f2_t ff2  = pack2(fff2.x, fff2.y);     // (F, F^2) = the FFF field
            f2_t ffp  = pack2(fff2.x, fff2.x);
            f2_t aabb = mul2(ab, ab);
            f2_t afbf = mul2(ab, ffp);
            #pragma unroll
            for (int j = 0; j < 2; j++) {
                int k = ii - j;
                if (k >= 0 && k < WIN) {
                    fma2(aAB[j],   GSYM(k), ab);
                    fma2(aAABB[j], GSYM(k), aabb);
                    fma2(aAFBF[j], GSYM(k), afbf);
                    fma2(aFFF[j],  GSYM(k), ff2);
                }
            }
        }
        int o = r * PHB + c0;
        #pragma unroll
        for (int j = 0; j < 2; j++) {
            hb0[o + j] = make_ulonglong2(aAB[j],   aAABB[j]);
            hb1[o + j] = make_ulonglong2(aAFBF[j], aFFF[j]);
        }
    }
    __syncthreads();

    // ---- vertical pass: 12 groups x 3 rows = 36 = TSY exactly; no clamp ----
    const int vc = tid & 31;
    const int r0 = (tid >> 5) * 3;    // 0,3,...,33; max read row 33+12=45=INWY-1

    f2_t vAB[3], vAABB[3], vAFBF[3], vFFF[3];
    #pragma unroll
    for (int j = 0; j < 3; j++) { vAB[j]=0; vAABB[j]=0; vAFBF[j]=0; vFFF[j]=0; }

    #pragma unroll
    for (int ii = 0; ii < 13; ii++) {
        int o = (r0 + ii) * PHB + vc;
        ulonglong2 h0 = hb0[o];
        ulonglong2 h1 = hb1[o];
        #pragma unroll
        for (int j = 0; j < 3; j++) {
            int k = ii - j;
            if (k >= 0 && k < WIN) {
                fma2(vAB[j],   GSYM(k), h0.x);
                fma2(vAABB[j], GSYM(k), h0.y);
                fma2(vAFBF[j], GSYM(k), h1.x);
                fma2(vFFF[j],  GSYM(k), h1.y);
            }
        }
    }

    float local = 0.f;
    const int gy_base = blockIdx.y * TSY + r0;
    #pragma unroll
    for (int j = 0; j < 3; j++) {
        if (gy_base + j < 512) {
            float muA, muB, eAA, eBB, eAF, eBF, muF, eFF;
            unpack2(vAB[j],   muA, muB);
            unpack2(vAABB[j], eAA, eBB);
            unpack2(vAFBF[j], eAF, eBF);
            unpack2(vFFF[j],  muF, eFF);
            local += ssim_val(muA, muF, eAA, eFF, eAF);
            local += ssim_val(muB, muF, eBB, eFF, eBF);
        }
    }

    // ---- block reduction (12 warps) ----
    #pragma unroll
    for (int o = 16; o > 0; o >>= 1)
        local += __shfl_down_sync(0xffffffffu, local, o);
    if ((tid & 31) == 0) red[tid >> 5] = local;
    __syncthreads();

    const int bid = blockIdx.x + 16 * blockIdx.y + (16 * GRIDY) * blockIdx.z;
    __shared__ bool is_last;
    if (tid == 0) {
        float v = 0.f;
        #pragma unroll
        for (int w = 0; w < NWARPS; w++) v += red[w];
        g_partials[bid] = v;
        __threadfence();
        unsigned int old = atomicAdd(&g_done, 1u);
        is_last = (old == NBLOCKS - 1);
    }
    __syncthreads();

    if (is_last) {
        double s = 0.0;
        for (int i = tid; i < NBLOCKS; i += NTHREADS)
            s += (double)__ldcg(&g_partials[i]);
        #pragma unroll
        for (int o = 16; o > 0; o >>= 1)
            s += __shfl_down_sync(0xffffffffu, s, o);
        double* redd = (double*)red;
        if ((tid & 31) == 0) redd[tid >> 5] = s;
        __syncthreads();
        if (tid == 0) {
            double t = 0.0;
            #pragma unroll
            for (int w = 0; w < NWARPS; w++) t += redd[w];
            out[0] = (float)(0.5 * t / 12582912.0);
            g_done = 0;
        }
    }
}

extern "C" void kernel_launch(void* const* d_in, const int* in_sizes, int n_in,
                              void* d_out, int out_size) {
    const float* A = (const float*)d_in[0];
    const float* B = (const float*)d_in[1];
    const float* F = (const float*)d_in[2];

    GW gw;
    double gd[WIN], s = 0.0;
    for (int i = 0; i < WIN; i++) {
        double d = (double)(i - RAD);
        gd[i] = exp(-(d * d) / (2.0 * 1.5 * 1.5));
        s += gd[i];
    }
    for (int i = 0; i < WIN; i++) gw.g[i] = (float)(gd[i] / s);

    cudaFuncSetAttribute(ssim_tile_kernel,
                         cudaFuncAttributeMaxDynamicSharedMemorySize, SMEM_BYTES);

    dim3 grid(512 / TSX, GRIDY, 16 * 3);
    ssim_tile_kernel<<<grid, NTHREADS, SMEM_BYTES>>>(A, B, F, gw, (float*)d_out);
}